// round 13
// baseline (speedup 1.0000x reference)
#include <cuda_runtime.h>
#include <cuda_bf16.h>
#include <stdint.h>
#include <math.h>

#define NROWS 8192
#define NDIM  384
#define EPSV  1e-8f

#define BM 128
#define BN 128
#define NB (NROWS / BM)            // 64
#define NTILES (NB * (NB + 1) / 2) // 2080
#define NSEG 148                   // persistent CTAs
#define NKS (NDIM / 32)            // 12 k-steps of 32 (IMMA k32)

#define ASB 400                    // int8 smem row stride (384 + 16 pad)
#define ABYTES (BM * ASB)          // 51200
#define SM_A   0
#define SM_B   51200               // 2 buffers of ABYTES
#define SM_SA  153600              // 128 floats (row scales, resident)
#define SM_SB  154112              // 2 x 128 floats (col scales)
#define RED_OFF 155136             // 32 KB reduction scratch
#define SMEM_TOTAL (RED_OFF + 32768)   // 187904

#define DIST_BLOCKS 1024

// Scratch (static device memory; no allocations)
__device__ __align__(16) float g_x[(size_t)NROWS * NDIM];      // fp32 (distances)
__device__ __align__(16) signed char g_xq[(size_t)NROWS * NDIM]; // int8 rows
__device__ float g_s[NROWS];                                    // per-row scale
__device__ unsigned long long g_best[NROWS];                    // packed (val,idx)
__device__ float g_part[DIST_BLOCKS];
__device__ unsigned g_tick;

__device__ __forceinline__ void ldsm_x4(unsigned& r0, unsigned& r1,
                                        unsigned& r2, unsigned& r3,
                                        unsigned addr) {
    asm volatile("ldmatrix.sync.aligned.m8n8.x4.shared.b16 {%0,%1,%2,%3}, [%4];"
                 : "=r"(r0), "=r"(r1), "=r"(r2), "=r"(r3) : "r"(addr));
}
__device__ __forceinline__ void imma16832(int* c, const unsigned* a,
                                          const unsigned* b) {
    asm volatile("mma.sync.aligned.m16n8k32.row.col.s32.s8.s8.s32 "
                 "{%0,%1,%2,%3}, {%4,%5,%6,%7}, {%8,%9}, {%0,%1,%2,%3};"
                 : "+r"(c[0]), "+r"(c[1]), "+r"(c[2]), "+r"(c[3])
                 : "r"(a[0]), "r"(a[1]), "r"(a[2]), "r"(a[3]),
                   "r"(b[0]), "r"(b[1]));
}
__device__ __forceinline__ void cp_async16(unsigned dst, const void* src) {
    asm volatile("cp.async.cg.shared.global [%0], [%1], 16;"
                 :: "r"(dst), "l"(src) : "memory");
}
__device__ __forceinline__ void cp_commit() {
    asm volatile("cp.async.commit_group;" ::: "memory");
}
__device__ __forceinline__ void cp_wait1() {
    asm volatile("cp.async.wait_group 1;" ::: "memory");
}
__device__ __forceinline__ void cp_wait0() {
    asm volatile("cp.async.wait_group 0;" ::: "memory");
}
__device__ __forceinline__ unsigned long long pack_best(float v, int idx) {
    unsigned u = __float_as_uint(v);
    u = (u & 0x80000000u) ? ~u : (u | 0x80000000u);
    return ((unsigned long long)u << 32) | (unsigned)(0xFFFFFFFFu - (unsigned)idx);
}
__device__ __forceinline__ void decode_tile(int t, int& bi, int& bj) {
    int b = 0, rem = t;
    while (rem >= NB - b) { rem -= NB - b; b++; }
    bi = b; bj = b + rem;
}

// ---------------------------------------------------------------------------
// Kernel 1: L2 normalize rows; emit fp32 copy, per-row int8 quant + scale.
// ---------------------------------------------------------------------------
__global__ void koleo_normalize(const float* __restrict__ in) {
    int gwarp = (blockIdx.x * blockDim.x + threadIdx.x) >> 5;
    int lane = threadIdx.x & 31;
    if (blockIdx.x == 0 && threadIdx.x == 0) g_tick = 0;
    if (gwarp >= NROWS) return;

    const float4* a4 = (const float4*)(in + (size_t)gwarp * NDIM);
    float4 v[3];
    float ss = 0.0f;
#pragma unroll
    for (int t = 0; t < 3; t++) {
        v[t] = a4[lane + 32 * t];
        ss = fmaf(v[t].x, v[t].x, ss);
        ss = fmaf(v[t].y, v[t].y, ss);
        ss = fmaf(v[t].z, v[t].z, ss);
        ss = fmaf(v[t].w, v[t].w, ss);
    }
#pragma unroll
    for (int o = 16; o > 0; o >>= 1)
        ss += __shfl_xor_sync(0xffffffffu, ss, o);
    float inv = 1.0f / fmaxf(sqrtf(ss), EPSV);

    float4 w[3];
    float ma = 0.0f;
    float4* o4 = (float4*)(g_x + (size_t)gwarp * NDIM);
#pragma unroll
    for (int t = 0; t < 3; t++) {
        w[t].x = v[t].x * inv; w[t].y = v[t].y * inv;
        w[t].z = v[t].z * inv; w[t].w = v[t].w * inv;
        o4[lane + 32 * t] = w[t];
        ma = fmaxf(ma, fmaxf(fmaxf(fabsf(w[t].x), fabsf(w[t].y)),
                             fmaxf(fabsf(w[t].z), fabsf(w[t].w))));
    }
#pragma unroll
    for (int o = 16; o > 0; o >>= 1)
        ma = fmaxf(ma, __shfl_xor_sync(0xffffffffu, ma, o));

    float invs = 127.0f / ma;
    if (lane == 0) {
        g_s[gwarp] = ma * (1.0f / 127.0f);
        g_best[gwarp] = 0ull;
    }

    int* q32 = (int*)g_xq + (size_t)gwarp * (NDIM / 4);
#pragma unroll
    for (int t = 0; t < 3; t++) {
        int q0 = __float2int_rn(w[t].x * invs);
        int q1 = __float2int_rn(w[t].y * invs);
        int q2 = __float2int_rn(w[t].z * invs);
        int q3 = __float2int_rn(w[t].w * invs);
        q32[lane + 32 * t] = (q0 & 0xFF) | ((q1 & 0xFF) << 8) |
                             ((q2 & 0xFF) << 16) | (q3 << 24);
    }
}

// ---------------------------------------------------------------------------
// Kernel 2: persistent upper-triangle int8 IMMA Gram tiles (148 CTAs).
// A block + row scales smem-resident per bi-run; full-B double buffered with
// cross-tile prefetch; row argmax in registers across the run.
// ---------------------------------------------------------------------------
__global__ void __launch_bounds__(256, 1) koleo_argmax(unsigned long long* __restrict__ best) {
    extern __shared__ __align__(16) unsigned char smraw[];
    const unsigned smb = (unsigned)__cvta_generic_to_shared(smraw);
    const unsigned smA = smb + SM_A;
    const unsigned smB = smb + SM_B;

    const int tid = threadIdx.x;
    const int wid = tid >> 5;
    const int lane = tid & 31;
    const int wm = wid >> 2;
    const int wn = wid & 3;
    const int r_in_warp = lane >> 2;
    const int c_in_quad = (lane & 3) * 2;

    const int t_begin = (int)(((long long)blockIdx.x * NTILES) / NSEG);
    const int t_end   = (int)(((long long)(blockIdx.x + 1) * NTILES) / NSEG);

    float* sSA = (float*)(smraw + SM_SA);
    float* sSB = (float*)(smraw + SM_SB);      // [buf*128 + i]
    float* rv = (float*)(smraw + RED_OFF);
    int*   ri = (int*)(smraw + RED_OFF + 8192);
    float* cv = (float*)(smraw + RED_OFF + 16384);
    int*   ci = (int*)(smraw + RED_OFF + 24576);

    const unsigned as_off = (wm * 64 + (lane & 15)) * ASB + (lane >> 4) * 16;
    const unsigned bs_off = (wn * 32 + (lane >> 4) * 8 + (lane & 7)) * ASB +
                            ((lane >> 3) & 1) * 16;

    auto issue_A = [&](int bi) {
#pragma unroll
        for (int i = 0; i < 12; i++) {
            int q = i * 256 + tid;
            int r = q / 24, c = q % 24;
            cp_async16(smA + r * ASB + c * 16,
                       (const void*)(g_xq + (size_t)(bi * BM + r) * NDIM + c * 16));
        }
        if (tid < 32)
            cp_async16(smb + SM_SA + tid * 16, (const void*)(g_s + bi * BM + tid * 4));
    };
    auto issue_B = [&](int bj, int buf) {
        const unsigned bb = smB + buf * ABYTES;
#pragma unroll
        for (int i = 0; i < 12; i++) {
            int q = i * 256 + tid;
            int r = q / 24, c = q % 24;
            cp_async16(bb + r * ASB + c * 16,
                       (const void*)(g_xq + (size_t)(bj * BM + r) * NDIM + c * 16));
        }
        if (tid < 32)
            cp_async16(smb + SM_SB + buf * 512 + tid * 16,
                       (const void*)(g_s + bj * BM + tid * 4));
    };

    float rbv[8];
    int   rbx[8];
#pragma unroll
    for (int i = 0; i < 8; i++) { rbv[i] = -1e9f; rbx[i] = 0x7fffffff; }

    int bi, bj;
    decode_tile(t_begin, bi, bj);
    int a_bi = bi;
    issue_A(bi);
    issue_B(bj, 0);
    cp_commit();
    int par = 0;

    for (int t = t_begin; t < t_end; ++t) {
        const bool has_next = (t + 1 < t_end);
        int nbi = -1, nbj = -1;
        if (has_next) decode_tile(t + 1, nbi, nbj);
        const bool diag = (bi == bj);
        const bool boundary = has_next && (nbi != a_bi);

        // Prefetch next tile's B if A is unchanged.
        bool prefetched = false;
        if (has_next && !boundary) {
            issue_B(nbj, par ^ 1); cp_commit(); prefetched = true;
        }
        if (prefetched) cp_wait1(); else cp_wait0();
        __syncthreads();

        int acc[4][4][4];
#pragma unroll
        for (int mi = 0; mi < 4; mi++)
#pragma unroll
            for (int ni = 0; ni < 4; ni++)
#pragma unroll
                for (int r = 0; r < 4; r++) acc[mi][ni][r] = 0;

        const unsigned as_base = smA + as_off;
        const unsigned bs_base = smB + par * ABYTES + bs_off;
#pragma unroll
        for (int ks = 0; ks < NKS; ++ks) {
            const unsigned koff = ks * 32;

            unsigned afr[4][4];
#pragma unroll
            for (int mi = 0; mi < 4; mi++)
                ldsm_x4(afr[mi][0], afr[mi][1], afr[mi][2], afr[mi][3],
                        as_base + mi * 16 * ASB + koff);

            unsigned bfr[4][2];
#pragma unroll
            for (int p = 0; p < 2; p++) {
                unsigned r0, r1, r2, r3;
                ldsm_x4(r0, r1, r2, r3, bs_base + p * 16 * ASB + koff);
                bfr[p * 2 + 0][0] = r0; bfr[p * 2 + 0][1] = r1;
                bfr[p * 2 + 1][0] = r2; bfr[p * 2 + 1][1] = r3;
            }

#pragma unroll
            for (int mi = 0; mi < 4; mi++)
#pragma unroll
                for (int ni = 0; ni < 4; ni++)
                    imma16832(acc[mi][ni], afr[mi], bfr[ni]);
        }
        __syncthreads();

        // Scales into registers BEFORE any boundary overwrite of smA/sSA.
        float si8[8], sj8[8];
#pragma unroll
        for (int mi = 0; mi < 4; mi++)
#pragma unroll
            for (int h = 0; h < 2; h++)
                si8[mi * 2 + h] = sSA[wm * 64 + mi * 16 + r_in_warp + 8 * h];
#pragma unroll
        for (int ni = 0; ni < 4; ni++)
#pragma unroll
            for (int cc = 0; cc < 2; cc++)
                sj8[ni * 2 + cc] = sSB[par * 128 + wn * 32 + ni * 8 + c_in_quad + cc];

        if (boundary) {
            __syncthreads();          // everyone done reading smA / sSA
            issue_A(nbi);
            issue_B(nbj, par ^ 1);
            cp_commit();
            a_bi = nbi;
        }

        // ===== Epilogue (value = cand_scale * acc; owner scale drops out) =====
        const bool flush = !has_next || (nbi != bi);

#pragma unroll
        for (int mi = 0; mi < 4; mi++) {
#pragma unroll
            for (int h = 0; h < 2; h++) {
                const int six = mi * 2 + h;
                const int gi = bi * BM + wm * 64 + mi * 16 + r_in_warp + 8 * h;
                float bv = rbv[six]; int bx = rbx[six];
#pragma unroll
                for (int ni = 0; ni < 4; ni++) {
#pragma unroll
                    for (int cc = 0; cc < 2; cc++) {
                        float v = (float)acc[mi][ni][h * 2 + cc] * sj8[ni * 2 + cc];
                        int gj = bj * BN + wn * 32 + ni * 8 + c_in_quad + cc;
                        if (gi != gj && (v > bv || (v == bv && gj < bx))) {
                            bv = v; bx = gj;
                        }
                    }
                }
                rbv[six] = bv; rbx[six] = bx;
            }
        }

        if (!diag) {
#pragma unroll
            for (int ni = 0; ni < 4; ni++) {
#pragma unroll
                for (int cc = 0; cc < 2; cc++) {
                    const int lc = wn * 32 + ni * 8 + c_in_quad + cc;
                    float bv = -1e9f; int bx = 0x7fffffff;
#pragma unroll
                    for (int mi = 0; mi < 4; mi++) {
#pragma unroll
                        for (int h = 0; h < 2; h++) {
                            float v = (float)acc[mi][ni][h * 2 + cc] * si8[mi * 2 + h];
                            int gi = bi * BM + wm * 64 + mi * 16 + r_in_warp + 8 * h;
                            if (v > bv || (v == bv && gi < bx)) { bv = v; bx = gi; }
                        }
                    }
                    cv[lc * 16 + wm * 8 + r_in_warp] = bv;
                    ci[lc * 16 + wm * 8 + r_in_warp] = bx;
                }
            }
        }
        if (flush) {
#pragma unroll
            for (int mi = 0; mi < 4; mi++) {
#pragma unroll
                for (int h = 0; h < 2; h++) {
                    const int lr = wm * 64 + mi * 16 + r_in_warp + 8 * h;
                    rv[lr * 16 + wn * 4 + (lane & 3)] = rbv[mi * 2 + h];
                    ri[lr * 16 + wn * 4 + (lane & 3)] = rbx[mi * 2 + h];
                }
            }
        }

        if (!diag || flush) {
            __syncthreads();
            if (!diag && tid < BM) {
                float bv = -1e9f; int bx = 0x7fffffff;
#pragma unroll
                for (int s = 0; s < 16; s++) {
                    float v = cv[tid * 16 + s];
                    int ix = ci[tid * 16 + s];
                    if (v > bv || (v == bv && ix < bx)) { bv = v; bx = ix; }
                }
                atomicMax(&best[bj * BN + tid], pack_best(bv, bx));
            }
            if (flush && tid >= BM) {
                const int row = tid - BM;
                float bv = -1e9f; int bx = 0x7fffffff;
#pragma unroll
                for (int s = 0; s < 16; s++) {
                    float v = rv[row * 16 + s];
                    int ix = ri[row * 16 + s];
                    if (v > bv || (v == bv && ix < bx)) { bv = v; bx = ix; }
                }
                atomicMax(&best[bi * BM + row], pack_best(bv, bx));
            }
        }
        if (flush) {
#pragma unroll
            for (int i = 0; i < 8; i++) { rbv[i] = -1e9f; rbx[i] = 0x7fffffff; }
        }

        if (has_next) { bi = nbi; bj = nbj; }
        par ^= 1;
    }
}

// ---------------------------------------------------------------------------
// Kernel 3: decode neighbor, log pairwise distance, fused final reduction.
// ---------------------------------------------------------------------------
__global__ void koleo_dist_reduce(float* __restrict__ out) {
    __shared__ float spart[8];
    __shared__ unsigned slast;

    int gwarp = (blockIdx.x * blockDim.x + threadIdx.x) >> 5;
    int wid = threadIdx.x >> 5;
    int lane = threadIdx.x & 31;

    float lg = 0.0f;
    if (gwarp < NROWS) {
        unsigned long long key = g_best[gwarp];
        int bi = (int)(0xFFFFFFFFu - (unsigned)(key & 0xFFFFFFFFull));

        const float4* a4 = (const float4*)(g_x + (size_t)gwarp * NDIM);
        const float4* b4 = (const float4*)(g_x + (size_t)bi * NDIM);
        float ss = 0.0f;
#pragma unroll
        for (int t = 0; t < 3; t++) {
            float4 a = a4[lane + 32 * t];
            float4 b = b4[lane + 32 * t];
            float dx = a.x - b.x + EPSV;
            float dy = a.y - b.y + EPSV;
            float dz = a.z - b.z + EPSV;
            float dw = a.w - b.w + EPSV;
            ss = fmaf(dx, dx, ss);
            ss = fmaf(dy, dy, ss);
            ss = fmaf(dz, dz, ss);
            ss = fmaf(dw, dw, ss);
        }
#pragma unroll
        for (int o = 16; o > 0; o >>= 1)
            ss += __shfl_xor_sync(0xffffffffu, ss, o);
        lg = logf(sqrtf(ss) + EPSV);
    }
    if (lane == 0) spart[wid] = lg;
    __syncthreads();

    if (threadIdx.x == 0) {
        float acc = 0.0f;
#pragma unroll
        for (int w = 0; w < 8; w++) acc += spart[w];
        g_part[blockIdx.x] = acc;
        __threadfence();
        unsigned t = atomicAdd(&g_tick, 1u);
        slast = (t == DIST_BLOCKS - 1) ? 1u : 0u;
    }
    __syncthreads();

    if (slast) {
        float acc = 0.0f;
        for (int i = threadIdx.x; i < DIST_BLOCKS; i += 256) acc += g_part[i];
        __shared__ float s[256];
        s[threadIdx.x] = acc;
        __syncthreads();
        for (int w = 128; w > 0; w >>= 1) {
            if (threadIdx.x < w) s[threadIdx.x] += s[threadIdx.x + w];
            __syncthreads();
        }
        if (threadIdx.x == 0) out[0] = -s[0] / (float)NROWS;
    }
}

// ---------------------------------------------------------------------------
extern "C" void kernel_launch(void* const* d_in, const int* in_sizes, int n_in,
                              void* d_out, int out_size) {
    const float* in = (const float*)d_in[0];
    float* out = (float*)d_out;

    koleo_normalize<<<(NROWS * 32 + 255) / 256, 256>>>(in);

    cudaFuncSetAttribute(koleo_argmax, cudaFuncAttributeMaxDynamicSharedMemorySize,
                         SMEM_TOTAL);
    unsigned long long* best = nullptr;
    cudaGetSymbolAddress((void**)&best, g_best);
    koleo_argmax<<<NSEG, 256, SMEM_TOTAL>>>(best);

    koleo_dist_reduce<<<DIST_BLOCKS, 256>>>(out);
}

// round 17
// speedup vs baseline: 1.9258x; 1.9258x over previous
#include <cuda_runtime.h>
#include <cuda_bf16.h>
#include <stdint.h>
#include <math.h>

#define NROWS 8192
#define NDIM  384
#define EPSV  1e-8f

#define BM 128
#define BN 128
#define NB (NROWS / BM)            // 64
#define NTILES (NB * (NB + 1) / 2) // 2080
#define NSEG 152                   // persistent CTAs (one per GB300 SM)
#define KC 128                     // k per B chunk
#define NCHUNK (NDIM / KC)         // 3

#define ASB 784                    // A smem row stride bytes (768 + 16)
#define ABYTES (BM * ASB)          // 100352
#define BSB 272                    // B smem row stride bytes (256 + 16)
#define BBUF (BM * BSB)            // 34816
#define RED_OFF (ABYTES + 2 * BBUF)        // 169984
#define SMEM_TOTAL (RED_OFF + 32768)       // 202752

#define DIST_BLOCKS 1024

// Scratch (static device memory; no allocations)
__device__ __align__(16) float g_x[(size_t)NROWS * NDIM];            // fp32 (distances)
__device__ __align__(16) __nv_bfloat16 g_xh[(size_t)NROWS * NDIM];   // bf16 (HMMA)
__device__ unsigned long long g_best[NROWS];                          // packed (val,idx)
__device__ float g_part[DIST_BLOCKS];                                 // per-block partials
__device__ unsigned g_tick;                                           // completion ticket

__device__ __forceinline__ void ldsm_x4(unsigned& r0, unsigned& r1,
                                        unsigned& r2, unsigned& r3,
                                        unsigned addr) {
    asm volatile("ldmatrix.sync.aligned.m8n8.x4.shared.b16 {%0,%1,%2,%3}, [%4];"
                 : "=r"(r0), "=r"(r1), "=r"(r2), "=r"(r3) : "r"(addr));
}
__device__ __forceinline__ void mma16816(float* c, const unsigned* a,
                                         const unsigned* b) {
    asm volatile("mma.sync.aligned.m16n8k16.row.col.f32.bf16.bf16.f32 "
                 "{%0,%1,%2,%3}, {%4,%5,%6,%7}, {%8,%9}, {%0,%1,%2,%3};"
                 : "+f"(c[0]), "+f"(c[1]), "+f"(c[2]), "+f"(c[3])
                 : "r"(a[0]), "r"(a[1]), "r"(a[2]), "r"(a[3]),
                   "r"(b[0]), "r"(b[1]));
}
__device__ __forceinline__ void cp_async16(unsigned dst, const void* src) {
    asm volatile("cp.async.cg.shared.global [%0], [%1], 16;"
                 :: "r"(dst), "l"(src) : "memory");
}
__device__ __forceinline__ void cp_commit() {
    asm volatile("cp.async.commit_group;" ::: "memory");
}
__device__ __forceinline__ void cp_wait1() {
    asm volatile("cp.async.wait_group 1;" ::: "memory");
}
__device__ __forceinline__ void cp_wait0() {
    asm volatile("cp.async.wait_group 0;" ::: "memory");
}
__device__ __forceinline__ unsigned long long pack_best(float v, int idx) {
    unsigned u = __float_as_uint(v);
    u = (u & 0x80000000u) ? ~u : (u | 0x80000000u);
    return ((unsigned long long)u << 32) | (unsigned)(0xFFFFFFFFu - (unsigned)idx);
}
__device__ __forceinline__ void decode_tile(int t, int& bi, int& bj) {
    int b = 0, rem = t;
    while (rem >= NB - b) { rem -= NB - b; b++; }
    bi = b; bj = b + rem;
}

// ---------------------------------------------------------------------------
// Kernel 1: L2 normalize rows (warp/row); resets g_best and ticket.
// ---------------------------------------------------------------------------
__global__ void koleo_normalize(const float* __restrict__ in) {
    int gwarp = (blockIdx.x * blockDim.x + threadIdx.x) >> 5;
    int lane = threadIdx.x & 31;
    if (blockIdx.x == 0 && threadIdx.x == 0) g_tick = 0;
    if (gwarp >= NROWS) return;

    const float4* a4 = (const float4*)(in + (size_t)gwarp * NDIM);
    float4 v[3];
    float ss = 0.0f;
#pragma unroll
    for (int t = 0; t < 3; t++) {
        v[t] = a4[lane + 32 * t];
        ss = fmaf(v[t].x, v[t].x, ss);
        ss = fmaf(v[t].y, v[t].y, ss);
        ss = fmaf(v[t].z, v[t].z, ss);
        ss = fmaf(v[t].w, v[t].w, ss);
    }
#pragma unroll
    for (int o = 16; o > 0; o >>= 1)
        ss += __shfl_xor_sync(0xffffffffu, ss, o);

    float inv = 1.0f / fmaxf(sqrtf(ss), EPSV);

    if (lane == 0) g_best[gwarp] = 0ull;

    float4* o4 = (float4*)(g_x + (size_t)gwarp * NDIM);
    __nv_bfloat162* h2 = (__nv_bfloat162*)(g_xh + (size_t)gwarp * NDIM);
#pragma unroll
    for (int t = 0; t < 3; t++) {
        float4 w;
        w.x = v[t].x * inv; w.y = v[t].y * inv;
        w.z = v[t].z * inv; w.w = v[t].w * inv;
        o4[lane + 32 * t] = w;
        __nv_bfloat162 p0, p1;
        p0.x = __float2bfloat16_rn(w.x); p0.y = __float2bfloat16_rn(w.y);
        p1.x = __float2bfloat16_rn(w.z); p1.y = __float2bfloat16_rn(w.w);
        h2[(lane + 32 * t) * 2 + 0] = p0;
        h2[(lane + 32 * t) * 2 + 1] = p1;
    }
}

// ---------------------------------------------------------------------------
// Kernel 2: persistent upper-triangle Gram tiles (152 CTAs, 13-14 tiles each).
// A block smem-resident across a bi-run; B double-buffered, cross-tile
// chunk-0 prefetch; run-boundary A load hidden under the flush epilogue.
// ---------------------------------------------------------------------------
__global__ void __launch_bounds__(256, 1) koleo_argmax(unsigned long long* __restrict__ best) {
    extern __shared__ __align__(16) unsigned char smraw[];
    const unsigned smb = (unsigned)__cvta_generic_to_shared(smraw);
    const unsigned smA = smb;
    const unsigned smB = smb + ABYTES;

    const int tid = threadIdx.x;
    const int wid = tid >> 5;
    const int lane = tid & 31;
    const int wm = wid >> 2;
    const int wn = wid & 3;
    const int r_in_warp = lane >> 2;
    const int c_in_quad = (lane & 3) * 2;

    const int t_begin = (int)(((long long)blockIdx.x * NTILES) / NSEG);
    const int t_end   = (int)(((long long)(blockIdx.x + 1) * NTILES) / NSEG);

    float* rv = (float*)(smraw + RED_OFF);
    int*   ri = (int*)(smraw + RED_OFF + 8192);
    float* cv = (float*)(smraw + RED_OFF + 16384);
    int*   ci = (int*)(smraw + RED_OFF + 24576);

    const unsigned as_off = (wm * 64 + (lane & 15)) * ASB + (lane >> 4) * 16;
    const unsigned bs_off = (wn * 32 + (lane & 15)) * BSB + (lane >> 4) * 16;

    auto issue_A = [&](int bi) {
#pragma unroll
        for (int i = 0; i < 24; i++) {
            int q = i * 256 + tid;
            int r = q / 48, c = q % 48;
            cp_async16(smA + r * ASB + c * 16,
                       (const void*)(g_xh + (size_t)(bi * BM + r) * NDIM + c * 8));
        }
    };
    auto issue_B = [&](int bj, int chunk, int buf) {
        const unsigned bb = smB + buf * BBUF;
        const size_t kof = (size_t)chunk * KC;
#pragma unroll
        for (int i = 0; i < 8; i++) {
            int q = i * 256 + tid;
            int r = q >> 4, s = q & 15;
            cp_async16(bb + r * BSB + s * 16,
                       (const void*)(g_xh + (size_t)(bj * BM + r) * NDIM + kof + s * 8));
        }
    };

    float rbv[8];
    int   rbx[8];
#pragma unroll
    for (int i = 0; i < 8; i++) { rbv[i] = -2.0f; rbx[i] = 0x7fffffff; }

    int bi, bj;
    decode_tile(t_begin, bi, bj);
    int a_bi = bi;
    issue_A(bi);
    issue_B(bj, 0, 0);
    cp_commit();
    int par = 0;

    for (int t = t_begin; t < t_end; ++t) {
        const bool has_next = (t + 1 < t_end);
        int nbi = -1, nbj = -1;
        if (has_next) decode_tile(t + 1, nbi, nbj);
        const bool diag = (bi == bj);
        const bool boundary = has_next && (nbi != a_bi);

        float acc[4][4][4];
#pragma unroll
        for (int mi = 0; mi < 4; mi++)
#pragma unroll
            for (int ni = 0; ni < 4; ni++)
#pragma unroll
                for (int r = 0; r < 4; r++) acc[mi][ni][r] = 0.0f;

#pragma unroll
        for (int c = 0; c < NCHUNK; c++) {
            bool issued = false;
            if (c < NCHUNK - 1) {
                issue_B(bj, c + 1, par ^ 1); cp_commit(); issued = true;
            } else if (has_next && !boundary) {
                issue_B(nbj, 0, par ^ 1); cp_commit(); issued = true;  // prefetch
            }
            if (issued) cp_wait1(); else cp_wait0();
            __syncthreads();

            const unsigned as_base = smA + as_off;
            const unsigned bs_base = smB + par * BBUF + bs_off;
#pragma unroll
            for (int ksc = 0; ksc < KC / 16; ++ksc) {
                const unsigned akoff = (c * 8 + ksc) * 32;
                const unsigned bkoff = ksc * 32;

                unsigned afr[4][4];
#pragma unroll
                for (int mi = 0; mi < 4; mi++)
                    ldsm_x4(afr[mi][0], afr[mi][1], afr[mi][2], afr[mi][3],
                            as_base + mi * 16 * ASB + akoff);

                unsigned bfr[4][2];
#pragma unroll
                for (int np = 0; np < 2; np++) {
                    unsigned r0, r1, r2, r3;
                    ldsm_x4(r0, r1, r2, r3, bs_base + np * 16 * BSB + bkoff);
                    bfr[np * 2 + 0][0] = r0; bfr[np * 2 + 0][1] = r2;
                    bfr[np * 2 + 1][0] = r1; bfr[np * 2 + 1][1] = r3;
                }

#pragma unroll
                for (int mi = 0; mi < 4; mi++)
#pragma unroll
                    for (int ni = 0; ni < 4; ni++)
                        mma16816(acc[mi][ni], afr[mi], bfr[ni]);
            }
            __syncthreads();
            par ^= 1;
        }

        // Run-boundary: issue next run's A + B chunk-0 now; the loads are
        // hidden under the epilogue below. Safe: chunk loop ended with
        // __syncthreads, so all warps are done reading smA.
        if (boundary) {
            issue_A(nbi);
            issue_B(nbj, 0, par);
            cp_commit();
            a_bi = nbi;
        }

        // ===== Epilogue =====
        const bool flush = !has_next || (nbi != bi);

        // Row direction: accumulate in registers (run-long).
#pragma unroll
        for (int mi = 0; mi < 4; mi++) {
#pragma unroll
            for (int h = 0; h < 2; h++) {
                const int six = mi * 2 + h;
                const int gi = bi * BM + wm * 64 + mi * 16 + r_in_warp + 8 * h;
                float bv = rbv[six]; int bx = rbx[six];
#pragma unroll
                for (int ni = 0; ni < 4; ni++) {
#pragma unroll
                    for (int cc = 0; cc < 2; cc++) {
                        float v = acc[mi][ni][h * 2 + cc];
                        int gj = bj * BN + wn * 32 + ni * 8 + c_in_quad + cc;
                        if (gi != gj && (v > bv || (v == bv && gj < bx))) {
                            bv = v; bx = gj;
                        }
                    }
                }
                rbv[six] = bv; rbx[six] = bx;
            }
        }

        // Column candidates to smem (off-diagonal tiles only).
        if (!diag) {
#pragma unroll
            for (int ni = 0; ni < 4; ni++) {
#pragma unroll
                for (int cc = 0; cc < 2; cc++) {
                    const int lc = wn * 32 + ni * 8 + c_in_quad + cc;
                    float bv = -2.0f; int bx = 0x7fffffff;
#pragma unroll
                    for (int mi = 0; mi < 4; mi++) {
#pragma unroll
                        for (int h = 0; h < 2; h++) {
                            float v = acc[mi][ni][h * 2 + cc];
                            int gi = bi * BM + wm * 64 + mi * 16 + r_in_warp + 8 * h;
                            if (v > bv || (v == bv && gi < bx)) { bv = v; bx = gi; }
                        }
                    }
                    cv[lc * 16 + wm * 8 + r_in_warp] = bv;
                    ci[lc * 16 + wm * 8 + r_in_warp] = bx;
                }
            }
        }
        if (flush) {
#pragma unroll
            for (int mi = 0; mi < 4; mi++) {
#pragma unroll
                for (int h = 0; h < 2; h++) {
                    const int lr = wm * 64 + mi * 16 + r_in_warp + 8 * h;
                    rv[lr * 16 + wn * 4 + (lane & 3)] = rbv[mi * 2 + h];
                    ri[lr * 16 + wn * 4 + (lane & 3)] = rbx[mi * 2 + h];
                }
            }
        }

        if (!diag || flush) {
            __syncthreads();
            if (!diag && tid < BM) {
                float bv = -2.0f; int bx = 0x7fffffff;
#pragma unroll
                for (int s = 0; s < 16; s++) {
                    float v = cv[tid * 16 + s];
                    int ix = ci[tid * 16 + s];
                    if (v > bv || (v == bv && ix < bx)) { bv = v; bx = ix; }
                }
                atomicMax(&best[bj * BN + tid], pack_best(bv, bx));
            }
            if (flush && tid >= BM) {
                const int row = tid - BM;
                float bv = -2.0f; int bx = 0x7fffffff;
#pragma unroll
                for (int s = 0; s < 16; s++) {
                    float v = rv[row * 16 + s];
                    int ix = ri[row * 16 + s];
                    if (v > bv || (v == bv && ix < bx)) { bv = v; bx = ix; }
                }
                atomicMax(&best[bi * BM + row], pack_best(bv, bx));
            }
        }
        if (flush) {
#pragma unroll
            for (int i = 0; i < 8; i++) { rbv[i] = -2.0f; rbx[i] = 0x7fffffff; }
        }

        if (has_next) { bi = nbi; bj = nbj; }
    }
}

// ---------------------------------------------------------------------------
// Kernel 3: decode neighbor, log pairwise distance, fused final reduction.
// Warp per row; per-block partial -> last finished block sums (deterministic:
// fixed-order array sum) and writes the loss.
// ---------------------------------------------------------------------------
__global__ void koleo_dist_reduce(float* __restrict__ out) {
    __shared__ float spart[8];
    __shared__ unsigned slast;

    int gwarp = (blockIdx.x * blockDim.x + threadIdx.x) >> 5;
    int wid = threadIdx.x >> 5;
    int lane = threadIdx.x & 31;

    float lg = 0.0f;
    if (gwarp < NROWS) {
        unsigned long long key = g_best[gwarp];
        int bi = (int)(0xFFFFFFFFu - (unsigned)(key & 0xFFFFFFFFull));

        const float4* a4 = (const float4*)(g_x + (size_t)gwarp * NDIM);
        const float4* b4 = (const float4*)(g_x + (size_t)bi * NDIM);
        float ss = 0.0f;
#pragma unroll
        for (int t = 0; t < 3; t++) {
            float4 a = a4[lane + 32 * t];
            float4 b = b4[lane + 32 * t];
            float dx = a.x - b.x + EPSV;
            float dy = a.y - b.y + EPSV;
            float dz = a.z - b.z + EPSV;
            float dw = a.w - b.w + EPSV;
            ss = fmaf(dx, dx, ss);
            ss = fmaf(dy, dy, ss);
            ss = fmaf(dz, dz, ss);
            ss = fmaf(dw, dw, ss);
        }
#pragma unroll
        for (int o = 16; o > 0; o >>= 1)
            ss += __shfl_xor_sync(0xffffffffu, ss, o);
        lg = logf(sqrtf(ss) + EPSV);
    }
    if (lane == 0) spart[wid] = lg;
    __syncthreads();

    if (threadIdx.x == 0) {
        float acc = 0.0f;
#pragma unroll
        for (int w = 0; w < 8; w++) acc += spart[w];
        g_part[blockIdx.x] = acc;
        __threadfence();
        unsigned t = atomicAdd(&g_tick, 1u);
        slast = (t == DIST_BLOCKS - 1) ? 1u : 0u;
    }
    __syncthreads();

    if (slast) {
        // Last block: deterministic fixed-order sum of all partials.
        float acc = 0.0f;
        for (int i = threadIdx.x; i < DIST_BLOCKS; i += 256) acc += g_part[i];
        __shared__ float s[256];
        s[threadIdx.x] = acc;
        __syncthreads();
        for (int w = 128; w > 0; w >>= 1) {
            if (threadIdx.x < w) s[threadIdx.x] += s[threadIdx.x + w];
            __syncthreads();
        }
        if (threadIdx.x == 0) out[0] = -s[0] / (float)NROWS;
    }
}

// ---------------------------------------------------------------------------
extern "C" void kernel_launch(void* const* d_in, const int* in_sizes, int n_in,
                              void* d_out, int out_size) {
    const float* in = (const float*)d_in[0];
    float* out = (float*)d_out;

    koleo_normalize<<<(NROWS * 32 + 255) / 256, 256>>>(in);

    cudaFuncSetAttribute(koleo_argmax, cudaFuncAttributeMaxDynamicSharedMemorySize,
                         SMEM_TOTAL);
    unsigned long long* best = nullptr;
    cudaGetSymbolAddress((void**)&best, g_best);
    koleo_argmax<<<NSEG, 256, SMEM_TOTAL>>>(best);

    koleo_dist_reduce<<<DIST_BLOCKS, 256>>>(out);
}